// round 5
// baseline (speedup 1.0000x reference)
#include <cuda_runtime.h>
#include <cuda_bf16.h>

#define IMG_W 512
#define IMG_H 512
#define SUBROWS 32          // rows per warp strip
#define NTHREADS 128        // 4 warps: (colhalf = w&1, subband = w>>1)

// 3x3 local variance, stride 1, zero pad 1, divisor 9.
// Warp-autonomous: each lane owns 8 contiguous columns (2x LDG.128 per row).
// Rolling state per lane: previous-row values vp[8], pair sums p[8] (last two
// rows) and pair square-sums q[8]. Vertical 3-sum = p + current, then
// horizontal 3-sum via warp shuffles; warp-boundary column kept as scalar
// rolling state in lanes 0/31.
__global__ __launch_bounds__(NTHREADS, 8)
void ChannelwiseVariance_85091892068508_kernel(const float* __restrict__ x,
                                               float* __restrict__ out)
{
    const int tid  = threadIdx.x;
    const int lane = tid & 31;
    const int w    = tid >> 5;
    const int colhalf = w & 1;
    const int sub     = w >> 1;
    const int col  = colhalf * 256 + lane * 8;     // first of 8 owned columns
    const int y0   = blockIdx.x * (2 * SUBROWS) + sub * SUBROWS;
    const size_t plane = (size_t)blockIdx.y * (size_t)(IMG_H * IMG_W);

    const bool has_left  = (col != 0);
    const bool has_right = (col + 8 != IMG_W);
    const float inv9 = 1.0f / 9.0f;

    float vp[8], p[8], q[8];
    #pragma unroll
    for (int j = 0; j < 8; ++j) { vp[j] = 0.f; p[j] = 0.f; q[j] = 0.f; }
    // boundary-column rolling state (lanes 0 / 31)
    float lxp = 0.f, lp = 0.f, lq = 0.f;
    float rxp = 0.f, rp = 0.f, rq = 0.f;

    #pragma unroll 2
    for (int it = 0; it < SUBROWS + 2; ++it) {
        const int r = y0 - 1 + it;
        const bool rvalid = (r >= 0) && (r < IMG_H);
        const size_t rowoff = plane + (size_t)r * IMG_W;

        float4 va = make_float4(0.f, 0.f, 0.f, 0.f);
        float4 vb = make_float4(0.f, 0.f, 0.f, 0.f);
        float lxn = 0.f, rxn = 0.f;
        if (rvalid) {
            va = *reinterpret_cast<const float4*>(x + rowoff + col);
            vb = *reinterpret_cast<const float4*>(x + rowoff + col + 4);
        }
        if (lane == 0 && rvalid && has_left)   lxn = x[rowoff + col - 1];
        if (lane == 31 && rvalid && has_right) rxn = x[rowoff + col + 8];

        float vc[8];
        vc[0] = va.x; vc[1] = va.y; vc[2] = va.z; vc[3] = va.w;
        vc[4] = vb.x; vc[5] = vb.y; vc[6] = vb.z; vc[7] = vb.w;

        // Vertical 3-sums for output row r-1, then roll state forward.
        float S1[8], S2[8];
        #pragma unroll
        for (int j = 0; j < 8; ++j) {
            const float sq = vc[j] * vc[j];
            S1[j] = p[j] + vc[j];
            S2[j] = q[j] + sq;
            p[j]  = vp[j] + vc[j];
            q[j]  = fmaf(vp[j], vp[j], sq);
            vp[j] = vc[j];
        }
        // Boundary scalars (live in lanes 0 / 31).
        const float lsq = lxn * lxn, rsq = rxn * rxn;
        const float lS1 = lp + lxn, lS2 = lq + lsq;
        const float rS1 = rp + rxn, rS2 = rq + rsq;
        lp = lxp + lxn; lq = fmaf(lxp, lxp, lsq); lxp = lxn;
        rp = rxp + rxn; rq = fmaf(rxp, rxp, rsq); rxp = rxn;

        if (it >= 2) {
            // Horizontal halo of vertical sums via shuffles.
            float sv_l = __shfl_up_sync(0xffffffffu, S1[7], 1);
            float sq_l = __shfl_up_sync(0xffffffffu, S2[7], 1);
            float sv_r = __shfl_down_sync(0xffffffffu, S1[0], 1);
            float sq_r = __shfl_down_sync(0xffffffffu, S2[0], 1);
            if (lane == 0)  { sv_l = lS1; sq_l = lS2; }
            if (lane == 31) { sv_r = rS1; sq_r = rS2; }

            float o[8];
            {
                float t1 = sv_l + S1[0] + S1[1];
                float t2 = sq_l + S2[0] + S2[1];
                float m = t1 * inv9; o[0] = fmaf(-m, m, t2 * inv9);
            }
            #pragma unroll
            for (int j = 1; j < 7; ++j) {
                float t1 = S1[j - 1] + S1[j] + S1[j + 1];
                float t2 = S2[j - 1] + S2[j] + S2[j + 1];
                float m = t1 * inv9; o[j] = fmaf(-m, m, t2 * inv9);
            }
            {
                float t1 = S1[6] + S1[7] + sv_r;
                float t2 = S2[6] + S2[7] + sq_r;
                float m = t1 * inv9; o[7] = fmaf(-m, m, t2 * inv9);
            }

            const int y = r - 1;
            float* op = out + plane + (size_t)y * IMG_W + col;
            __stcs(reinterpret_cast<float4*>(op),
                   make_float4(o[0], o[1], o[2], o[3]));
            __stcs(reinterpret_cast<float4*>(op + 4),
                   make_float4(o[4], o[5], o[6], o[7]));
        }
    }
}

extern "C" void kernel_launch(void* const* d_in, const int* in_sizes, int n_in,
                              void* d_out, int out_size)
{
    const float* x = (const float*)d_in[0];
    float* out = (float*)d_out;

    const int planes = in_sizes[0] / (IMG_H * IMG_W);   // 8*32 = 256
    dim3 grid(IMG_H / (2 * SUBROWS), planes);           // (8, 256) = 2048 blocks
    dim3 block(NTHREADS);
    ChannelwiseVariance_85091892068508_kernel<<<grid, block>>>(x, out);
}